// round 6
// baseline (speedup 1.0000x reference)
#include <cuda_runtime.h>

#define CH_L   4096
#define CH_T   256
#define CH_SEG 16
#define NEG_INF (-1e30f)
#define LOG2E  1.4426950408889634f

typedef unsigned long long u64;

struct M2 { float a00, a01, a10, a11; };  // max-plus 2x2 operator (log2 domain)

__device__ __forceinline__ void step_vec(float& m0, float& m1, float c, float a) {
    float x0 = m0 - c;
    float x1 = m1 + c;
    m0 = fmaxf(x0 + a, x1 - a);
    m1 = fmaxf(x0 - a, x1 + a);
}
__device__ __forceinline__ void step_mat(M2& M, float c, float a) {
    step_vec(M.a00, M.a10, c, a);
    step_vec(M.a01, M.a11, c, a);
}
// C = A ∘ B (B first)
__device__ __forceinline__ M2 compose(const M2& A, const M2& B) {
    M2 C;
    C.a00 = fmaxf(A.a00 + B.a00, A.a01 + B.a10);
    C.a01 = fmaxf(A.a00 + B.a01, A.a01 + B.a11);
    C.a10 = fmaxf(A.a10 + B.a00, A.a11 + B.a10);
    C.a11 = fmaxf(A.a10 + B.a01, A.a11 + B.a11);
    return C;
}
__device__ __forceinline__ M2 m2_identity() { return M2{0.f, NEG_INF, NEG_INF, 0.f}; }

// apply matrix to the (0,0) vector: v_k = max_l M[k][l]
__device__ __forceinline__ void apply0(const M2& M, float& v0, float& v1) {
    v0 = fmaxf(M.a00, M.a01);
    v1 = fmaxf(M.a10, M.a11);
}
// apply matrix to vector (v0,v1)
__device__ __forceinline__ void applyv(const M2& M, float& v0, float& v1) {
    float r0 = fmaxf(M.a00 + v0, M.a01 + v1);
    float r1 = fmaxf(M.a10 + v0, M.a11 + v1);
    v0 = r0; v1 = r1;
}

// ---- packed f32x2 helpers ----
__device__ __forceinline__ u64 pk2(float lo, float hi) {
    u64 r; asm("mov.b64 %0, {%1,%2};" : "=l"(r) : "f"(lo), "f"(hi)); return r;
}
__device__ __forceinline__ void upk2(float& lo, float& hi, u64 v) {
    asm("mov.b64 {%0,%1}, %2;" : "=f"(lo), "=f"(hi) : "l"(v));
}
__device__ __forceinline__ u64 fadd2(u64 a, u64 b) {
    u64 r; asm("add.rn.f32x2 %0, %1, %2;" : "=l"(r) : "l"(a), "l"(b)); return r;
}
__device__ __forceinline__ float ex2(float x) {
    float r; asm("ex2.approx.f32 %0, %1;" : "=f"(r) : "f"(x)); return r;
}
__device__ __forceinline__ u64 step2(u64 m, u64 dc, u64 aa, u64 na) {
    u64 x = fadd2(m, dc);
    u64 p = fadd2(x, aa), q = fadd2(x, na);
    float pl, ph, ql, qh; upk2(pl, ph, p); upk2(ql, qh, q);
    return pk2(fmaxf(pl, qh), fmaxf(ql, ph));
}

__device__ __forceinline__ M2 shfl_up_m2(M2 m, int d) {
    M2 r;
    r.a00 = __shfl_up_sync(0xffffffffu, m.a00, d);
    r.a01 = __shfl_up_sync(0xffffffffu, m.a01, d);
    r.a10 = __shfl_up_sync(0xffffffffu, m.a10, d);
    r.a11 = __shfl_up_sync(0xffffffffu, m.a11, d);
    return r;
}
__device__ __forceinline__ M2 shfl_dn_m2(M2 m, int d) {
    M2 r;
    r.a00 = __shfl_down_sync(0xffffffffu, m.a00, d);
    r.a01 = __shfl_down_sync(0xffffffffu, m.a01, d);
    r.a10 = __shfl_down_sync(0xffffffffu, m.a10, d);
    r.a11 = __shfl_down_sync(0xffffffffu, m.a11, d);
    return r;
}

__global__ __launch_bounds__(CH_T)
void chain_bp_kernel(const float* __restrict__ jp,
                     const float* __restrict__ bp,
                     const int*   __restrict__ obs,
                     float*       __restrict__ out) {
    __shared__ unsigned int sbits[CH_L / 32];     // 128 words
    __shared__ float4 s_tab[256];                 // 8-step operator table (log2)
    __shared__ float  sb0[CH_L];                  // belief scratch state 0
    __shared__ float  sb1[CH_L];                  // belief scratch state 1
    __shared__ float4 s_wtF[8];
    __shared__ float4 s_wtB[8];

    const int row  = blockIdx.x;
    const int tid  = threadIdx.x;
    const int lane = tid & 31;
    const int wp   = tid >> 5;

    const float a  = 0.25f * jp[0] * LOG2E;
    const float c0 = 0.5f  * bp[0] * LOG2E;
    const float c1 = 0.5f  * bp[1] * LOG2E;

    // ---- 1a. coalesced obs -> 1 bit per position via ballot ----
    const int* orow = obs + (size_t)row * CH_L;
    #pragma unroll
    for (int t = tid; t < CH_L; t += CH_T) {
        int o = orow[t];
        unsigned int bal = __ballot_sync(0xffffffffu, o != 0);
        if (lane == 0) sbits[t >> 5] = bal;
    }

    // ---- 1b. build 8-step table in smem: each thread builds one entry ----
    {
        int x = tid;                // CH_T == 256 entries
        M2 M = m2_identity();
        #pragma unroll
        for (int k = 0; k < 8; k++) {
            float c = ((x >> k) & 1) ? c1 : c0;
            step_mat(M, c, a);
        }
        s_tab[x] = make_float4(M.a00, M.a01, M.a10, M.a11);
    }
    __syncthreads();

    // my 16 positions' bits
    const unsigned int w =
        (sbits[tid >> 1] >> ((tid & 1) * 16)) & 0xFFFFu;

    // ---- 2. segment operators from smem table ----
    float4 tlo = s_tab[w & 255u];
    float4 thi = s_tab[(w >> 8) & 255u];
    M2 F = compose(M2{thi.x, thi.y, thi.z, thi.w}, M2{tlo.x, tlo.y, tlo.z, tlo.w});

    float4 rlo = s_tab[__brev(w & 255u) >> 24];
    float4 rhi = s_tab[__brev((w >> 8) & 255u) >> 24];
    M2 Bm = compose(M2{rlo.x, rlo.y, rlo.z, rlo.w}, M2{rhi.x, rhi.y, rhi.z, rhi.w});

    // ---- 3. warp prefix scan (fwd) ----
    M2 curF = F;
    #pragma unroll
    for (int off = 1; off < 32; off <<= 1) {
        M2 l = shfl_up_m2(curF, off);
        if (lane >= off) curF = compose(curF, l);
    }
    if (lane == 31) s_wtF[wp] = make_float4(curF.a00, curF.a01, curF.a10, curF.a11);

    // ---- 4. warp suffix scan (bwd) ----
    M2 curB = Bm;
    #pragma unroll
    for (int off = 1; off < 32; off <<= 1) {
        M2 r = shfl_dn_m2(curB, off);
        if (lane + off < 32) curB = compose(curB, r);
    }
    if (lane == 0) s_wtB[wp] = make_float4(curB.a00, curB.a01, curB.a10, curB.a11);
    __syncthreads();

    // ---- 5. cross-warp combines. ALL 32 lanes of the warp execute every
    //         shuffle (collective); only the compose condition and the final
    //         store are guarded. Loads are clamped to stay in bounds. ----
    if (wp == 0) {
        float4 v = s_wtF[lane & 7];
        M2 M = M2{v.x, v.y, v.z, v.w};
        #pragma unroll
        for (int d = 1; d < 8; d <<= 1) {
            M2 l = shfl_up_m2(M, d);
            if (lane >= d && lane < 8) M = compose(M, l);
        }
        if (lane < 8) s_wtF[lane] = make_float4(M.a00, M.a01, M.a10, M.a11);
    }
    if (wp == 1) {
        float4 v = s_wtB[lane & 7];
        M2 M = M2{v.x, v.y, v.z, v.w};
        #pragma unroll
        for (int d = 1; d < 8; d <<= 1) {
            M2 r = shfl_dn_m2(M, d);
            if (lane + d < 8) M = compose(M, r);
        }
        if (lane < 8) s_wtB[lane] = make_float4(M.a00, M.a01, M.a10, M.a11);
    }
    __syncthreads();

    // ---- 6. boundary messages (vector form, start vector = (0,0)) ----
    float f0 = 0.f, f1 = 0.f;
    {
        float vc0 = 0.f, vc1 = 0.f;
        if (wp > 0) {
            float4 v = s_wtF[wp - 1];
            M2 C = M2{v.x, v.y, v.z, v.w};
            apply0(C, vc0, vc1);
        }
        M2 sp = shfl_up_m2(curF, 1);
        f0 = vc0; f1 = vc1;
        if (lane > 0) applyv(sp, f0, f1);
    }
    float g0 = 0.f, g1 = 0.f;    // bwd message at position base+SEG-1
    {
        float vc0 = 0.f, vc1 = 0.f;
        if (wp < 7) {
            float4 v = s_wtB[wp + 1];
            M2 C = M2{v.x, v.y, v.z, v.w};
            apply0(C, vc0, vc1);
        }
        M2 sn = shfl_dn_m2(curB, 1);
        g0 = vc0; g1 = vc1;
        if (lane < 31) applyv(sn, g0, g1);
    }

    // ---- packed constants ----
    const u64 dc0 = pk2(-c0,  c0);
    const u64 dc1 = pk2(-c1,  c1);
    const u64 aa  = pk2( a,   a);
    const u64 na  = pk2(-a,  -a);

    float4* pb0 = (float4*)sb0;
    float4* pb1 = (float4*)sb1;
    const int rowb = tid * 4;            // my 4 float4 slots per state
    const int rot  = tid >> 1;           // slot rotation (conflict-free phases)

    // ---- 7. forward replay: x[t] = phi+fwd, 4 steps buffered -> STS.128 ----
    u64 m = pk2(f0, f1);
    #pragma unroll
    for (int k4 = 0; k4 < 4; k4++) {
        float4 v0, v1;
        #pragma unroll
        for (int c = 0; c < 4; c++) {
            const int k = k4 * 4 + c;
            u64 dc = ((w >> k) & 1u) ? dc1 : dc0;
            u64 x = fadd2(m, dc);
            float x0s, x1s; upk2(x0s, x1s, x);
            if (c == 0)      { v0.x = x0s; v1.x = x1s; }
            else if (c == 1) { v0.y = x0s; v1.y = x1s; }
            else if (c == 2) { v0.z = x0s; v1.z = x1s; }
            else             { v0.w = x0s; v1.w = x1s; }
            u64 p = fadd2(x, aa), q = fadd2(x, na);
            float pl, ph, ql, qh; upk2(pl, ph, p); upk2(ql, qh, q);
            m = pk2(fmaxf(pl, qh), fmaxf(ql, ph));
        }
        const int slot = (k4 + rot) & 3;
        pb0[rowb + slot] = v0;
        pb1[rowb + slot] = v1;
    }

    // ---- 8. backward replay (self-slots only, no sync): belief = exp2(x+bwd) ----
    u64 n = pk2(g0, g1);
    #pragma unroll
    for (int k4 = 3; k4 >= 0; k4--) {
        float4 n0, n1;
        #pragma unroll
        for (int c = 3; c >= 0; c--) {
            const int k = k4 * 4 + c;
            float n0s, n1s; upk2(n0s, n1s, n);
            if (c == 0)      { n0.x = n0s; n1.x = n1s; }
            else if (c == 1) { n0.y = n0s; n1.y = n1s; }
            else if (c == 2) { n0.z = n0s; n1.z = n1s; }
            else             { n0.w = n0s; n1.w = n1s; }
            if (k > 0) {
                u64 dc = ((w >> k) & 1u) ? dc1 : dc0;
                n = step2(n, dc, aa, na);
            }
        }
        const int slot = (k4 + rot) & 3;
        float4 fv0 = pb0[rowb + slot];
        float4 fv1 = pb1[rowb + slot];
        u64 s0a = fadd2(pk2(fv0.x, fv0.y), pk2(n0.x, n0.y));
        u64 s0b = fadd2(pk2(fv0.z, fv0.w), pk2(n0.z, n0.w));
        u64 s1a = fadd2(pk2(fv1.x, fv1.y), pk2(n1.x, n1.y));
        u64 s1b = fadd2(pk2(fv1.z, fv1.w), pk2(n1.z, n1.w));
        float4 o0v, o1v; float lo, hi;
        upk2(lo, hi, s0a); o0v.x = ex2(lo); o0v.y = ex2(hi);
        upk2(lo, hi, s0b); o0v.z = ex2(lo); o0v.w = ex2(hi);
        upk2(lo, hi, s1a); o1v.x = ex2(lo); o1v.y = ex2(hi);
        upk2(lo, hi, s1b); o1v.z = ex2(lo); o1v.w = ex2(hi);
        pb0[rowb + slot] = o0v;
        pb1[rowb + slot] = o1v;
    }
    __syncthreads();

    // ---- 9. epilogue: LDS.128 -> STG.128 coalesced ----
    float4* o0 = (float4*)(out + (size_t)row * 2 * CH_L);
    float4* o1 = o0 + (CH_L / 4);
    #pragma unroll
    for (int it = 0; it < 4; it++) {
        const int u    = tid + CH_T * it;      // logical float4 index
        const int blk  = u >> 2;               // producing thread
        const int k4   = u & 3;
        const int slot = (k4 + (blk >> 1)) & 3;
        o0[u] = pb0[blk * 4 + slot];
        o1[u] = pb1[blk * 4 + slot];
    }
}

extern "C" void kernel_launch(void* const* d_in, const int* in_sizes, int n_in,
                              void* d_out, int out_size) {
    const float* jp  = (const float*)d_in[0];
    const float* bp  = (const float*)d_in[1];
    const int*   obs = (const int*)  d_in[2];
    float*       out = (float*)d_out;

    int B = in_sizes[2] / CH_L;
    chain_bp_kernel<<<B, CH_T>>>(jp, bp, obs, out);
}

// round 7
// speedup vs baseline: 1.0425x; 1.0425x over previous
#include <cuda_runtime.h>

#define CH_L   4096
#define CH_T   128
#define NEG_INF (-1e30f)
#define LOG2E  1.4426950408889634f

typedef unsigned long long u64;

struct M2 { float a00, a01, a10, a11; };  // max-plus 2x2 operator (log2 domain)

__device__ __forceinline__ void step_vec(float& m0, float& m1, float c, float a) {
    float x0 = m0 - c;
    float x1 = m1 + c;
    m0 = fmaxf(x0 + a, x1 - a);
    m1 = fmaxf(x0 - a, x1 + a);
}
__device__ __forceinline__ void step_mat(M2& M, float c, float a) {
    step_vec(M.a00, M.a10, c, a);
    step_vec(M.a01, M.a11, c, a);
}
// C = A ∘ B (B applied first)
__device__ __forceinline__ M2 compose(const M2& A, const M2& B) {
    M2 C;
    C.a00 = fmaxf(A.a00 + B.a00, A.a01 + B.a10);
    C.a01 = fmaxf(A.a00 + B.a01, A.a01 + B.a11);
    C.a10 = fmaxf(A.a10 + B.a00, A.a11 + B.a10);
    C.a11 = fmaxf(A.a10 + B.a01, A.a11 + B.a11);
    return C;
}
__device__ __forceinline__ M2 m2_identity() { return M2{0.f, NEG_INF, NEG_INF, 0.f}; }

// v = M · (0,0)
__device__ __forceinline__ void apply0(const M2& M, float& v0, float& v1) {
    v0 = fmaxf(M.a00, M.a01);
    v1 = fmaxf(M.a10, M.a11);
}
// v = M · v
__device__ __forceinline__ void applyv(const M2& M, float& v0, float& v1) {
    float r0 = fmaxf(M.a00 + v0, M.a01 + v1);
    float r1 = fmaxf(M.a10 + v0, M.a11 + v1);
    v0 = r0; v1 = r1;
}

// ---- packed f32x2 helpers ----
__device__ __forceinline__ u64 pk2(float lo, float hi) {
    u64 r; asm("mov.b64 %0, {%1,%2};" : "=l"(r) : "f"(lo), "f"(hi)); return r;
}
__device__ __forceinline__ void upk2(float& lo, float& hi, u64 v) {
    asm("mov.b64 {%0,%1}, %2;" : "=f"(lo), "=f"(hi) : "l"(v));
}
__device__ __forceinline__ u64 fadd2(u64 a, u64 b) {
    u64 r; asm("add.rn.f32x2 %0, %1, %2;" : "=l"(r) : "l"(a), "l"(b)); return r;
}
__device__ __forceinline__ float ex2(float x) {
    float r; asm("ex2.approx.f32 %0, %1;" : "=f"(r) : "f"(x)); return r;
}
__device__ __forceinline__ u64 step2(u64 m, u64 dc, u64 aa, u64 na) {
    u64 x = fadd2(m, dc);
    u64 p = fadd2(x, aa), q = fadd2(x, na);
    float pl, ph, ql, qh; upk2(pl, ph, p); upk2(ql, qh, q);
    return pk2(fmaxf(pl, qh), fmaxf(ql, ph));
}

// ---- 8-step operator table in global (built once, L2-resident) ----
__device__ float4 g_tab[256];

__global__ void build_tab_kernel(const float* __restrict__ jp,
                                 const float* __restrict__ bp) {
    int x = threadIdx.x;
    float a  = 0.25f * jp[0] * LOG2E;
    float c0 = 0.5f  * bp[0] * LOG2E;
    float c1 = 0.5f  * bp[1] * LOG2E;
    M2 M = m2_identity();
    #pragma unroll
    for (int k = 0; k < 8; k++) {
        float c = ((x >> k) & 1) ? c1 : c0;
        step_mat(M, c, a);
    }
    g_tab[x] = make_float4(M.a00, M.a01, M.a10, M.a11);
}

__device__ __forceinline__ M2 ld_tab(unsigned i) {
    float4 v = g_tab[i];
    return M2{v.x, v.y, v.z, v.w};
}
__device__ __forceinline__ M2 ld4(float4 v) { return M2{v.x, v.y, v.z, v.w}; }

__device__ __forceinline__ M2 shfl_up_m2(M2 m, int d) {
    M2 r;
    r.a00 = __shfl_up_sync(0xffffffffu, m.a00, d);
    r.a01 = __shfl_up_sync(0xffffffffu, m.a01, d);
    r.a10 = __shfl_up_sync(0xffffffffu, m.a10, d);
    r.a11 = __shfl_up_sync(0xffffffffu, m.a11, d);
    return r;
}
__device__ __forceinline__ M2 shfl_dn_m2(M2 m, int d) {
    M2 r;
    r.a00 = __shfl_down_sync(0xffffffffu, m.a00, d);
    r.a01 = __shfl_down_sync(0xffffffffu, m.a01, d);
    r.a10 = __shfl_down_sync(0xffffffffu, m.a10, d);
    r.a11 = __shfl_down_sync(0xffffffffu, m.a11, d);
    return r;
}

__global__ __launch_bounds__(CH_T)
void chain_bp_kernel(const float* __restrict__ jp,
                     const float* __restrict__ bp,
                     const int*   __restrict__ obs,
                     float*       __restrict__ out) {
    __shared__ float  sb0[CH_L];     // belief scratch state 0 (slot-rotated)
    __shared__ float  sb1[CH_L];     // belief scratch state 1
    __shared__ float4 s_wtF[4];
    __shared__ float4 s_wtB[4];

    const int row  = blockIdx.x;
    const int tid  = threadIdx.x;
    const int lane = tid & 31;
    const int wp   = tid >> 5;

    const float a  = 0.25f * jp[0] * LOG2E;
    const float c0 = 0.5f  * bp[0] * LOG2E;
    const float c1 = 0.5f  * bp[1] * LOG2E;

    // ---- 1. obs ingest, warp-local: lane k keeps ballot word k ----
    // warp wp owns positions [wp*1024, wp*1024+1023]; thread (wp,lane)'s
    // segment is positions (wp*32+lane)*32 .. +31 = ballot word `lane`.
    unsigned int w = 0;
    const int* orow = obs + (size_t)row * CH_L;
    const int wbase = wp << 10;
    #pragma unroll
    for (int i = 0; i < 32; i++) {
        int o = orow[wbase + (i << 5) + lane];
        unsigned int bal = __ballot_sync(0xffffffffu, o != 0);
        if (i == lane) w = bal;
    }

    // ---- 2. segment operators + partial composes (reused as chain seeds) ----
    M2 tb0 = ld_tab( w        & 255u);
    M2 tb1 = ld_tab((w >>  8) & 255u);
    M2 tb2 = ld_tab((w >> 16) & 255u);
    M2 tb3 = ld_tab((w >> 24) & 255u);
    M2 P2 = compose(tb1, tb0);
    M2 P3 = compose(tb2, P2);
    M2 F  = compose(tb3, P3);

    M2 uB0 = ld_tab(__brev( w        & 255u) >> 24);
    M2 uB1 = ld_tab(__brev((w >>  8) & 255u) >> 24);
    M2 uB2 = ld_tab(__brev((w >> 16) & 255u) >> 24);
    M2 uB3 = ld_tab(__brev((w >> 24) & 255u) >> 24);
    M2 U23  = compose(uB2, uB3);
    M2 U123 = compose(uB1, U23);
    M2 Bm   = compose(uB0, U123);

    // ---- 3. merged warp scans: fwd prefix + bwd suffix in one loop ----
    M2 curF = F, curB = Bm;
    #pragma unroll
    for (int off = 1; off < 32; off <<= 1) {
        M2 lF = shfl_up_m2(curF, off);
        M2 rB = shfl_dn_m2(curB, off);
        if (lane >= off)      curF = compose(curF, lF);
        if (lane + off < 32)  curB = compose(curB, rB);
    }
    if (lane == 31) s_wtF[wp] = make_float4(curF.a00, curF.a01, curF.a10, curF.a11);
    if (lane == 0)  s_wtB[wp] = make_float4(curB.a00, curB.a01, curB.a10, curB.a11);
    __syncthreads();

    // ---- 4. cross-warp carries (vector form, only 4 warps) ----
    float fc0 = 0.f, fc1 = 0.f;
    if (wp >= 1) { M2 T = ld4(s_wtF[0]); apply0(T, fc0, fc1); }
    if (wp >= 2) { M2 T = ld4(s_wtF[1]); applyv(T, fc0, fc1); }
    if (wp >= 3) { M2 T = ld4(s_wtF[2]); applyv(T, fc0, fc1); }
    float gc0 = 0.f, gc1 = 0.f;
    if (wp <= 2) { M2 T = ld4(s_wtB[3]); apply0(T, gc0, gc1); }
    if (wp <= 1) { M2 T = ld4(s_wtB[2]); applyv(T, gc0, gc1); }
    if (wp == 0) { M2 T = ld4(s_wtB[1]); applyv(T, gc0, gc1); }

    // within-warp boundary messages
    M2 sp = shfl_up_m2(curF, 1);
    float f0 = fc0, f1 = fc1;               // fwd msg at segment start
    if (lane > 0) applyv(sp, f0, f1);
    M2 sn = shfl_dn_m2(curB, 1);
    float g0 = gc0, g1 = gc1;               // bwd msg at segment end (pos base+31)
    if (lane < 31) applyv(sn, g0, g1);

    // ---- 5. chain seeds from partial composes (4-way ILP in replays) ----
    // fwd: msg entering byte j
    float fA0 = f0, fA1 = f1;                                   // pos 0
    float fB0 = f0, fB1 = f1; applyv(tb0, fB0, fB1);            // pos 8
    float fC0 = f0, fC1 = f1; applyv(P2,  fC0, fC1);            // pos 16
    float fD0 = f0, fD1 = f1; applyv(P3,  fD0, fD1);            // pos 24
    // bwd: msg at byte-top positions
    float gD0 = g0, gD1 = g1;                                   // pos 31
    float gC0 = g0, gC1 = g1; applyv(uB3,  gC0, gC1);           // pos 23
    float gB0 = g0, gB1 = g1; applyv(U23,  gB0, gB1);           // pos 15
    float gA0 = g0, gA1 = g1; applyv(U123, gA0, gA1);           // pos 7

    // ---- packed constants ----
    const u64 dc0p = pk2(-c0,  c0);
    const u64 dc1p = pk2(-c1,  c1);
    const u64 aa   = pk2( a,   a);
    const u64 na   = pk2(-a,  -a);

    float4* pb0 = (float4*)sb0;
    float4* pb1 = (float4*)sb1;
    const int rowb = tid * 8;        // my 8 float4 slots per state
    const int rot  = tid & 7;        // slot rotation (conflict-free quarter-warp)

    // ---- 6. forward replay: 4 independent 8-step chains ----
    u64 mch[4] = { pk2(fA0, fA1), pk2(fB0, fB1), pk2(fC0, fC1), pk2(fD0, fD1) };
    #pragma unroll
    for (int j = 0; j < 4; j++) {
        u64 m = mch[j];
        #pragma unroll
        for (int k4 = 0; k4 < 2; k4++) {
            float4 v0, v1;
            #pragma unroll
            for (int c = 0; c < 4; c++) {
                const int k = j * 8 + k4 * 4 + c;
                u64 dc = ((w >> k) & 1u) ? dc1p : dc0p;
                u64 x = fadd2(m, dc);
                float xl, xh; upk2(xl, xh, x);
                if (c == 0)      { v0.x = xl; v1.x = xh; }
                else if (c == 1) { v0.y = xl; v1.y = xh; }
                else if (c == 2) { v0.z = xl; v1.z = xh; }
                else             { v0.w = xl; v1.w = xh; }
                if (!(k4 == 1 && c == 3)) {           // last step unused
                    u64 p = fadd2(x, aa), q = fadd2(x, na);
                    float pl, ph, ql, qh; upk2(pl, ph, p); upk2(ql, qh, q);
                    m = pk2(fmaxf(pl, qh), fmaxf(ql, ph));
                }
            }
            const int slot = ((j * 2 + k4) + rot) & 7;
            pb0[rowb + slot] = v0;
            pb1[rowb + slot] = v1;
        }
    }

    // ---- 7. backward replay: 4 independent 8-step chains; combine + exp2 ----
    u64 nch[4] = { pk2(gA0, gA1), pk2(gB0, gB1), pk2(gC0, gC1), pk2(gD0, gD1) };
    #pragma unroll
    for (int j = 3; j >= 0; j--) {
        u64 n = nch[j];
        #pragma unroll
        for (int k4 = 1; k4 >= 0; k4--) {
            float4 n0, n1;
            #pragma unroll
            for (int c = 3; c >= 0; c--) {
                const int kk = k4 * 4 + c;           // local 7..0
                const int k  = j * 8 + kk;
                float nl, nh; upk2(nl, nh, n);
                if (c == 0)      { n0.x = nl; n1.x = nh; }
                else if (c == 1) { n0.y = nl; n1.y = nh; }
                else if (c == 2) { n0.z = nl; n1.z = nh; }
                else             { n0.w = nl; n1.w = nh; }
                if (kk > 0) {                        // step to position k-1
                    u64 dc = ((w >> k) & 1u) ? dc1p : dc0p;
                    n = step2(n, dc, aa, na);
                }
            }
            const int slot = ((j * 2 + k4) + rot) & 7;
            float4 fv0 = pb0[rowb + slot];
            float4 fv1 = pb1[rowb + slot];
            u64 s0a = fadd2(pk2(fv0.x, fv0.y), pk2(n0.x, n0.y));
            u64 s0b = fadd2(pk2(fv0.z, fv0.w), pk2(n0.z, n0.w));
            u64 s1a = fadd2(pk2(fv1.x, fv1.y), pk2(n1.x, n1.y));
            u64 s1b = fadd2(pk2(fv1.z, fv1.w), pk2(n1.z, n1.w));
            float4 o0v, o1v; float lo, hi;
            upk2(lo, hi, s0a); o0v.x = ex2(lo); o0v.y = ex2(hi);
            upk2(lo, hi, s0b); o0v.z = ex2(lo); o0v.w = ex2(hi);
            upk2(lo, hi, s1a); o1v.x = ex2(lo); o1v.y = ex2(hi);
            upk2(lo, hi, s1b); o1v.z = ex2(lo); o1v.w = ex2(hi);
            pb0[rowb + slot] = o0v;
            pb1[rowb + slot] = o1v;
        }
    }
    __syncthreads();

    // ---- 8. epilogue: LDS.128 -> STG.128 coalesced ----
    float4* o0 = (float4*)(out + (size_t)row * 2 * CH_L);
    float4* o1 = o0 + (CH_L / 4);
    #pragma unroll
    for (int it = 0; it < 8; it++) {
        const int u    = tid + CH_T * it;   // logical float4 index
        const int blk  = u >> 3;            // producing thread
        const int k4   = u & 7;
        const int slot = (k4 + (blk & 7)) & 7;
        o0[u] = pb0[blk * 8 + slot];
        o1[u] = pb1[blk * 8 + slot];
    }
}

extern "C" void kernel_launch(void* const* d_in, const int* in_sizes, int n_in,
                              void* d_out, int out_size) {
    const float* jp  = (const float*)d_in[0];
    const float* bp  = (const float*)d_in[1];
    const int*   obs = (const int*)  d_in[2];
    float*       out = (float*)d_out;

    int B = in_sizes[2] / CH_L;
    build_tab_kernel<<<1, 256>>>(jp, bp);
    chain_bp_kernel<<<B, CH_T>>>(jp, bp, obs, out);
}

// round 8
// speedup vs baseline: 1.0431x; 1.0006x over previous
#include <cuda_runtime.h>

#define CH_L   4096
#define CH_T   128
#define NEG_INF (-1e30f)
#define LOG2E  1.4426950408889634f

typedef unsigned long long u64;

struct M2 { float a00, a01, a10, a11; };  // max-plus 2x2 operator (log2 domain)

__device__ __forceinline__ void step_vec(float& m0, float& m1, float c, float a) {
    float x0 = m0 - c;
    float x1 = m1 + c;
    m0 = fmaxf(x0 + a, x1 - a);
    m1 = fmaxf(x0 - a, x1 + a);
}
__device__ __forceinline__ void step_mat(M2& M, float c, float a) {
    step_vec(M.a00, M.a10, c, a);
    step_vec(M.a01, M.a11, c, a);
}
// C = A ∘ B (B applied first)
__device__ __forceinline__ M2 compose(const M2& A, const M2& B) {
    M2 C;
    C.a00 = fmaxf(A.a00 + B.a00, A.a01 + B.a10);
    C.a01 = fmaxf(A.a00 + B.a01, A.a01 + B.a11);
    C.a10 = fmaxf(A.a10 + B.a00, A.a11 + B.a10);
    C.a11 = fmaxf(A.a10 + B.a01, A.a11 + B.a11);
    return C;
}
__device__ __forceinline__ M2 m2_identity() { return M2{0.f, NEG_INF, NEG_INF, 0.f}; }

// v = M · (0,0)
__device__ __forceinline__ void apply0(const M2& M, float& v0, float& v1) {
    v0 = fmaxf(M.a00, M.a01);
    v1 = fmaxf(M.a10, M.a11);
}
// v = M · v
__device__ __forceinline__ void applyv(const M2& M, float& v0, float& v1) {
    float r0 = fmaxf(M.a00 + v0, M.a01 + v1);
    float r1 = fmaxf(M.a10 + v0, M.a11 + v1);
    v0 = r0; v1 = r1;
}

// ---- packed f32x2 helpers ----
__device__ __forceinline__ u64 pk2(float lo, float hi) {
    u64 r; asm("mov.b64 %0, {%1,%2};" : "=l"(r) : "f"(lo), "f"(hi)); return r;
}
__device__ __forceinline__ void upk2(float& lo, float& hi, u64 v) {
    asm("mov.b64 {%0,%1}, %2;" : "=f"(lo), "=f"(hi) : "l"(v));
}
__device__ __forceinline__ u64 fadd2(u64 a, u64 b) {
    u64 r; asm("add.rn.f32x2 %0, %1, %2;" : "=l"(r) : "l"(a), "l"(b)); return r;
}
__device__ __forceinline__ float ex2(float x) {
    float r; asm("ex2.approx.f32 %0, %1;" : "=f"(r) : "f"(x)); return r;
}
__device__ __forceinline__ u64 step2(u64 m, u64 dc, u64 aa, u64 na) {
    u64 x = fadd2(m, dc);
    u64 p = fadd2(x, aa), q = fadd2(x, na);
    float pl, ph, ql, qh; upk2(pl, ph, p); upk2(ql, qh, q);
    return pk2(fmaxf(pl, qh), fmaxf(ql, ph));
}

// ---- 8-step operator table in global (built once, L2/L1-resident) ----
__device__ float4 g_tab[256];

__global__ void build_tab_kernel(const float* __restrict__ jp,
                                 const float* __restrict__ bp) {
    int x = threadIdx.x;
    float a  = 0.25f * jp[0] * LOG2E;
    float c0 = 0.5f  * bp[0] * LOG2E;
    float c1 = 0.5f  * bp[1] * LOG2E;
    M2 M = m2_identity();
    #pragma unroll
    for (int k = 0; k < 8; k++) {
        float c = ((x >> k) & 1) ? c1 : c0;
        step_mat(M, c, a);
    }
    g_tab[x] = make_float4(M.a00, M.a01, M.a10, M.a11);
}

__device__ __forceinline__ M2 ld_tab(unsigned i) {
    float4 v = g_tab[i];
    return M2{v.x, v.y, v.z, v.w};
}
__device__ __forceinline__ M2 ld4(float4 v) { return M2{v.x, v.y, v.z, v.w}; }

__device__ __forceinline__ M2 shfl_up_m2(M2 m, int d) {
    M2 r;
    r.a00 = __shfl_up_sync(0xffffffffu, m.a00, d);
    r.a01 = __shfl_up_sync(0xffffffffu, m.a01, d);
    r.a10 = __shfl_up_sync(0xffffffffu, m.a10, d);
    r.a11 = __shfl_up_sync(0xffffffffu, m.a11, d);
    return r;
}
__device__ __forceinline__ M2 shfl_dn_m2(M2 m, int d) {
    M2 r;
    r.a00 = __shfl_down_sync(0xffffffffu, m.a00, d);
    r.a01 = __shfl_down_sync(0xffffffffu, m.a01, d);
    r.a10 = __shfl_down_sync(0xffffffffu, m.a10, d);
    r.a11 = __shfl_down_sync(0xffffffffu, m.a11, d);
    return r;
}

__global__ __launch_bounds__(CH_T, 6)
void chain_bp_kernel(const float* __restrict__ jp,
                     const float* __restrict__ bp,
                     const int*   __restrict__ obs,
                     float*       __restrict__ out) {
    __shared__ float  sb0[CH_L];     // belief scratch state 0 (slot-rotated)
    __shared__ float  sb1[CH_L];     // belief scratch state 1
    __shared__ float4 s_wtF[4];
    __shared__ float4 s_wtB[4];

    const int row  = blockIdx.x;
    const int tid  = threadIdx.x;
    const int lane = tid & 31;
    const int wp   = tid >> 5;

    const float a  = 0.25f * jp[0] * LOG2E;
    const float c0 = 0.5f  * bp[0] * LOG2E;
    const float c1 = 0.5f  * bp[1] * LOG2E;

    // ---- 1. obs ingest, warp-local: lane k keeps ballot word k ----
    unsigned int w = 0;
    const int* orow = obs + (size_t)row * CH_L;
    const int wbase = wp << 10;
    #pragma unroll
    for (int i = 0; i < 32; i++) {
        int o = orow[wbase + (i << 5) + lane];
        unsigned int bal = __ballot_sync(0xffffffffu, o != 0);
        if (i == lane) w = bal;
    }

    // ---- 2. segment operators + partial composes (reused as chain seeds) ----
    M2 tb0 = ld_tab( w        & 255u);
    M2 tb1 = ld_tab((w >>  8) & 255u);
    M2 tb2 = ld_tab((w >> 16) & 255u);
    M2 tb3 = ld_tab((w >> 24) & 255u);
    M2 P2 = compose(tb1, tb0);                 // operator for bits 0..15
    M2 F  = compose(tb3, compose(tb2, P2));

    M2 uB0 = ld_tab(__brev( w        & 255u) >> 24);
    M2 uB1 = ld_tab(__brev((w >>  8) & 255u) >> 24);
    M2 uB2 = ld_tab(__brev((w >> 16) & 255u) >> 24);
    M2 uB3 = ld_tab(__brev((w >> 24) & 255u) >> 24);
    M2 U23 = compose(uB2, uB3);                // bwd operator for positions 16..31
    M2 Bm  = compose(uB0, compose(uB1, U23));

    // ---- 3. merged warp scans: fwd prefix + bwd suffix in one loop ----
    M2 curF = F, curB = Bm;
    #pragma unroll
    for (int off = 1; off < 32; off <<= 1) {
        M2 lF = shfl_up_m2(curF, off);
        M2 rB = shfl_dn_m2(curB, off);
        if (lane >= off)      curF = compose(curF, lF);
        if (lane + off < 32)  curB = compose(curB, rB);
    }
    if (lane == 31) s_wtF[wp] = make_float4(curF.a00, curF.a01, curF.a10, curF.a11);
    if (lane == 0)  s_wtB[wp] = make_float4(curB.a00, curB.a01, curB.a10, curB.a11);
    __syncthreads();

    // ---- 4. cross-warp carries (vector form, only 4 warps) ----
    float fc0 = 0.f, fc1 = 0.f;
    if (wp >= 1) { M2 T = ld4(s_wtF[0]); apply0(T, fc0, fc1); }
    if (wp >= 2) { M2 T = ld4(s_wtF[1]); applyv(T, fc0, fc1); }
    if (wp >= 3) { M2 T = ld4(s_wtF[2]); applyv(T, fc0, fc1); }
    float gc0 = 0.f, gc1 = 0.f;
    if (wp <= 2) { M2 T = ld4(s_wtB[3]); apply0(T, gc0, gc1); }
    if (wp <= 1) { M2 T = ld4(s_wtB[2]); applyv(T, gc0, gc1); }
    if (wp == 0) { M2 T = ld4(s_wtB[1]); applyv(T, gc0, gc1); }

    // within-warp boundary messages
    M2 sp = shfl_up_m2(curF, 1);
    float f0 = fc0, f1 = fc1;               // fwd msg at segment start (pos 0)
    if (lane > 0) applyv(sp, f0, f1);
    M2 sn = shfl_dn_m2(curB, 1);
    float g0 = gc0, g1 = gc1;               // bwd msg at segment end (pos 31)
    if (lane < 31) applyv(sn, g0, g1);

    // ---- packed constants ----
    const u64 dc0p = pk2(-c0,  c0);
    const u64 dc1p = pk2(-c1,  c1);
    const u64 aa   = pk2( a,   a);
    const u64 na   = pk2(-a,  -a);

    float4* pb0 = (float4*)sb0;
    float4* pb1 = (float4*)sb1;
    const int rowb = tid * 8;        // my 8 float4 slots per state
    const int rot  = tid & 7;        // slot rotation (conflict-free quarter-warp)

    // ---- 5. forward replay: 2 interleaved 16-step chains (pos 0.., pos 16..) ----
    u64 mA = pk2(f0, f1);
    float fB0 = f0, fB1 = f1; applyv(P2, fB0, fB1);   // fwd msg at pos 16
    u64 mB = pk2(fB0, fB1);
    #pragma unroll
    for (int k4 = 0; k4 < 4; k4++) {
        float4 vA0, vA1, vB0, vB1;
        #pragma unroll
        for (int c = 0; c < 4; c++) {
            const int kA = k4 * 4 + c;
            const int kB = kA + 16;
            u64 dcA = ((w >> kA) & 1u) ? dc1p : dc0p;
            u64 dcB = ((w >> kB) & 1u) ? dc1p : dc0p;
            u64 xA = fadd2(mA, dcA);
            u64 xB = fadd2(mB, dcB);
            float al, ah, bl, bh; upk2(al, ah, xA); upk2(bl, bh, xB);
            if (c == 0)      { vA0.x = al; vA1.x = ah; vB0.x = bl; vB1.x = bh; }
            else if (c == 1) { vA0.y = al; vA1.y = ah; vB0.y = bl; vB1.y = bh; }
            else if (c == 2) { vA0.z = al; vA1.z = ah; vB0.z = bl; vB1.z = bh; }
            else             { vA0.w = al; vA1.w = ah; vB0.w = bl; vB1.w = bh; }
            if (!(k4 == 3 && c == 3)) {     // final step of each chain unused
                u64 pA = fadd2(xA, aa), qA = fadd2(xA, na);
                u64 pB = fadd2(xB, aa), qB = fadd2(xB, na);
                float p0,p1,q0,q1;
                upk2(p0,p1,pA); upk2(q0,q1,qA); mA = pk2(fmaxf(p0,q1), fmaxf(q0,p1));
                upk2(p0,p1,pB); upk2(q0,q1,qB); mB = pk2(fmaxf(p0,q1), fmaxf(q0,p1));
            }
        }
        const int sA = (k4 + rot) & 7;
        const int sB = (k4 + 4 + rot) & 7;
        pb0[rowb + sA] = vA0;  pb1[rowb + sA] = vA1;
        pb0[rowb + sB] = vB0;  pb1[rowb + sB] = vB1;
    }

    // ---- 6. backward replay: 2 interleaved chains; combine + exp2 fused ----
    u64 nB = pk2(g0, g1);                               // bwd at pos 31
    float gl0 = g0, gl1 = g1; applyv(U23, gl0, gl1);    // bwd at pos 15
    u64 nA = pk2(gl0, gl1);
    #pragma unroll
    for (int k4 = 3; k4 >= 0; k4--) {
        float4 nA0, nA1, nB0, nB1;
        #pragma unroll
        for (int c = 3; c >= 0; c--) {
            const int pA = k4 * 4 + c;                 // local pos 15..0
            const int pB = pA + 16;
            float al, ah, bl, bh; upk2(al, ah, nA); upk2(bl, bh, nB);
            if (c == 0)      { nA0.x = al; nA1.x = ah; nB0.x = bl; nB1.x = bh; }
            else if (c == 1) { nA0.y = al; nA1.y = ah; nB0.y = bl; nB1.y = bh; }
            else if (c == 2) { nA0.z = al; nA1.z = ah; nB0.z = bl; nB1.z = bh; }
            else             { nA0.w = al; nA1.w = ah; nB0.w = bl; nB1.w = bh; }
            if (pA > 0) {                              // step to pos-1 in each chain
                u64 dcA = ((w >> pA) & 1u) ? dc1p : dc0p;
                u64 dcB = ((w >> pB) & 1u) ? dc1p : dc0p;
                nA = step2(nA, dcA, aa, na);
                nB = step2(nB, dcB, aa, na);
            }
        }
        const int sA = (k4 + rot) & 7;
        const int sB = (k4 + 4 + rot) & 7;
        {
            float4 fv0 = pb0[rowb + sA];
            float4 fv1 = pb1[rowb + sA];
            u64 s0a = fadd2(pk2(fv0.x, fv0.y), pk2(nA0.x, nA0.y));
            u64 s0b = fadd2(pk2(fv0.z, fv0.w), pk2(nA0.z, nA0.w));
            u64 s1a = fadd2(pk2(fv1.x, fv1.y), pk2(nA1.x, nA1.y));
            u64 s1b = fadd2(pk2(fv1.z, fv1.w), pk2(nA1.z, nA1.w));
            float4 o0v, o1v; float lo, hi;
            upk2(lo, hi, s0a); o0v.x = ex2(lo); o0v.y = ex2(hi);
            upk2(lo, hi, s0b); o0v.z = ex2(lo); o0v.w = ex2(hi);
            upk2(lo, hi, s1a); o1v.x = ex2(lo); o1v.y = ex2(hi);
            upk2(lo, hi, s1b); o1v.z = ex2(lo); o1v.w = ex2(hi);
            pb0[rowb + sA] = o0v;
            pb1[rowb + sA] = o1v;
        }
        {
            float4 fv0 = pb0[rowb + sB];
            float4 fv1 = pb1[rowb + sB];
            u64 s0a = fadd2(pk2(fv0.x, fv0.y), pk2(nB0.x, nB0.y));
            u64 s0b = fadd2(pk2(fv0.z, fv0.w), pk2(nB0.z, nB0.w));
            u64 s1a = fadd2(pk2(fv1.x, fv1.y), pk2(nB1.x, nB1.y));
            u64 s1b = fadd2(pk2(fv1.z, fv1.w), pk2(nB1.z, nB1.w));
            float4 o0v, o1v; float lo, hi;
            upk2(lo, hi, s0a); o0v.x = ex2(lo); o0v.y = ex2(hi);
            upk2(lo, hi, s0b); o0v.z = ex2(lo); o0v.w = ex2(hi);
            upk2(lo, hi, s1a); o1v.x = ex2(lo); o1v.y = ex2(hi);
            upk2(lo, hi, s1b); o1v.z = ex2(lo); o1v.w = ex2(hi);
            pb0[rowb + sB] = o0v;
            pb1[rowb + sB] = o1v;
        }
    }
    __syncthreads();

    // ---- 7. epilogue: LDS.128 -> STG.128 coalesced ----
    float4* o0 = (float4*)(out + (size_t)row * 2 * CH_L);
    float4* o1 = o0 + (CH_L / 4);
    #pragma unroll
    for (int it = 0; it < 8; it++) {
        const int u    = tid + CH_T * it;   // logical float4 index
        const int blk  = u >> 3;            // producing thread
        const int k4   = u & 7;             // logical slot within thread
        const int slot = (k4 + (blk & 7)) & 7;
        o0[u] = pb0[blk * 8 + slot];
        o1[u] = pb1[blk * 8 + slot];
    }
}

extern "C" void kernel_launch(void* const* d_in, const int* in_sizes, int n_in,
                              void* d_out, int out_size) {
    const float* jp  = (const float*)d_in[0];
    const float* bp  = (const float*)d_in[1];
    const int*   obs = (const int*)  d_in[2];
    float*       out = (float*)d_out;

    int B = in_sizes[2] / CH_L;
    build_tab_kernel<<<1, 256>>>(jp, bp);
    chain_bp_kernel<<<B, CH_T>>>(jp, bp, obs, out);
}

// round 10
// speedup vs baseline: 1.0786x; 1.0340x over previous
#include <cuda_runtime.h>

#define CH_L   4096
#define CH_T   128
#define NEG_INF (-1e30f)
#define LOG2E  1.4426950408889634f

typedef unsigned long long u64;

struct M2 { float a00, a01, a10, a11; };  // max-plus 2x2 operator (log2 domain)

__device__ __forceinline__ void step_vec(float& m0, float& m1, float c, float a) {
    float x0 = m0 - c;
    float x1 = m1 + c;
    m0 = fmaxf(x0 + a, x1 - a);
    m1 = fmaxf(x0 - a, x1 + a);
}
__device__ __forceinline__ void step_mat(M2& M, float c, float a) {
    step_vec(M.a00, M.a10, c, a);
    step_vec(M.a01, M.a11, c, a);
}
// C = A ∘ B (B applied first)
__device__ __forceinline__ M2 compose(const M2& A, const M2& B) {
    M2 C;
    C.a00 = fmaxf(A.a00 + B.a00, A.a01 + B.a10);
    C.a01 = fmaxf(A.a00 + B.a01, A.a01 + B.a11);
    C.a10 = fmaxf(A.a10 + B.a00, A.a11 + B.a10);
    C.a11 = fmaxf(A.a10 + B.a01, A.a11 + B.a11);
    return C;
}
__device__ __forceinline__ M2 m2_identity() { return M2{0.f, NEG_INF, NEG_INF, 0.f}; }

// v = M · (0,0)
__device__ __forceinline__ void apply0(const M2& M, float& v0, float& v1) {
    v0 = fmaxf(M.a00, M.a01);
    v1 = fmaxf(M.a10, M.a11);
}
// v = M · v
__device__ __forceinline__ void applyv(const M2& M, float& v0, float& v1) {
    float r0 = fmaxf(M.a00 + v0, M.a01 + v1);
    float r1 = fmaxf(M.a10 + v0, M.a11 + v1);
    v0 = r0; v1 = r1;
}

// ---- packed f32x2 helpers ----
__device__ __forceinline__ u64 pk2(float lo, float hi) {
    u64 r; asm("mov.b64 %0, {%1,%2};" : "=l"(r) : "f"(lo), "f"(hi)); return r;
}
__device__ __forceinline__ void upk2(float& lo, float& hi, u64 v) {
    asm("mov.b64 {%0,%1}, %2;" : "=f"(lo), "=f"(hi) : "l"(v));
}
__device__ __forceinline__ u64 fadd2(u64 a, u64 b) {
    u64 r; asm("add.rn.f32x2 %0, %1, %2;" : "=l"(r) : "l"(a), "l"(b)); return r;
}
__device__ __forceinline__ float ex2(float x) {
    float r; asm("ex2.approx.f32 %0, %1;" : "=f"(r) : "f"(x)); return r;
}
__device__ __forceinline__ u64 step2(u64 m, u64 dc, u64 aa, u64 na) {
    u64 x = fadd2(m, dc);
    u64 p = fadd2(x, aa), q = fadd2(x, na);
    float pl, ph, ql, qh; upk2(pl, ph, p); upk2(ql, qh, q);
    return pk2(fmaxf(pl, qh), fmaxf(ql, ph));
}

__device__ __forceinline__ M2 ld4(float4 v) { return M2{v.x, v.y, v.z, v.w}; }

__device__ __forceinline__ M2 shfl_up_m2(M2 m, int d) {
    M2 r;
    r.a00 = __shfl_up_sync(0xffffffffu, m.a00, d);
    r.a01 = __shfl_up_sync(0xffffffffu, m.a01, d);
    r.a10 = __shfl_up_sync(0xffffffffu, m.a10, d);
    r.a11 = __shfl_up_sync(0xffffffffu, m.a11, d);
    return r;
}
__device__ __forceinline__ M2 shfl_dn_m2(M2 m, int d) {
    M2 r;
    r.a00 = __shfl_down_sync(0xffffffffu, m.a00, d);
    r.a01 = __shfl_down_sync(0xffffffffu, m.a01, d);
    r.a10 = __shfl_down_sync(0xffffffffu, m.a10, d);
    r.a11 = __shfl_down_sync(0xffffffffu, m.a11, d);
    return r;
}

__global__ __launch_bounds__(CH_T, 6)
void chain_bp_kernel(const float* __restrict__ jp,
                     const float* __restrict__ bp,
                     const int*   __restrict__ obs,
                     float*       __restrict__ out,
                     int nrows) {
    __shared__ float4 s_tab[256];    // 8-step operator table (log2 domain)
    __shared__ float  sb0[CH_L];     // belief scratch state 0 (slot-rotated)
    __shared__ float  sb1[CH_L];     // belief scratch state 1
    __shared__ float4 s_wtF[4];
    __shared__ float4 s_wtB[4];

    const int tid  = threadIdx.x;
    const int lane = tid & 31;
    const int wp   = tid >> 5;

    const float a  = 0.25f * jp[0] * LOG2E;
    const float c0 = 0.5f  * bp[0] * LOG2E;
    const float c1 = 0.5f  * bp[1] * LOG2E;

    // ---- 0. per-block table build: 2 entries per thread, amortized over rows ----
    #pragma unroll
    for (int e = 0; e < 2; e++) {
        int x = tid + e * CH_T;
        M2 M = m2_identity();
        #pragma unroll
        for (int k = 0; k < 8; k++) {
            float c = ((x >> k) & 1) ? c1 : c0;
            step_mat(M, c, a);
        }
        s_tab[x] = make_float4(M.a00, M.a01, M.a10, M.a11);
    }
    __syncthreads();

    // ---- packed constants ----
    const u64 dc0p = pk2(-c0,  c0);
    const u64 dc1p = pk2(-c1,  c1);
    const u64 aa   = pk2( a,   a);
    const u64 na   = pk2(-a,  -a);

    float4* pb0 = (float4*)sb0;
    float4* pb1 = (float4*)sb1;
    const int rowb = tid * 8;        // my 8 float4 slots per state
    const int rot  = tid & 7;        // slot rotation (conflict-free quarter-warp)
    const int wbase = wp << 10;

    for (int row = blockIdx.x; row < nrows; row += gridDim.x) {

        // ---- 1. obs ingest, warp-local: lane k keeps ballot word k ----
        unsigned int w = 0;
        const int* orow = obs + (size_t)row * CH_L;
        #pragma unroll
        for (int i = 0; i < 32; i++) {
            int o = orow[wbase + (i << 5) + lane];
            unsigned int bal = __ballot_sync(0xffffffffu, o != 0);
            if (i == lane) w = bal;
        }

        // ---- 2. segment operators + partial composes (chain seeds) ----
        M2 tb0 = ld4(s_tab[ w        & 255u]);
        M2 tb1 = ld4(s_tab[(w >>  8) & 255u]);
        M2 tb2 = ld4(s_tab[(w >> 16) & 255u]);
        M2 tb3 = ld4(s_tab[(w >> 24) & 255u]);
        M2 P2 = compose(tb1, tb0);                 // operator for bits 0..15
        M2 F  = compose(tb3, compose(tb2, P2));

        M2 uB0 = ld4(s_tab[__brev( w        & 255u) >> 24]);
        M2 uB1 = ld4(s_tab[__brev((w >>  8) & 255u) >> 24]);
        M2 uB2 = ld4(s_tab[__brev((w >> 16) & 255u) >> 24]);
        M2 uB3 = ld4(s_tab[__brev((w >> 24) & 255u) >> 24]);
        M2 U23 = compose(uB2, uB3);                // bwd operator for pos 16..31
        M2 Bm  = compose(uB0, compose(uB1, U23));

        // ---- 3. merged warp scans: fwd prefix + bwd suffix ----
        M2 curF = F, curB = Bm;
        #pragma unroll
        for (int off = 1; off < 32; off <<= 1) {
            M2 lF = shfl_up_m2(curF, off);
            M2 rB = shfl_dn_m2(curB, off);
            if (lane >= off)      curF = compose(curF, lF);
            if (lane + off < 32)  curB = compose(curB, rB);
        }
        if (lane == 31) s_wtF[wp] = make_float4(curF.a00, curF.a01, curF.a10, curF.a11);
        if (lane == 0)  s_wtB[wp] = make_float4(curB.a00, curB.a01, curB.a10, curB.a11);
        __syncthreads();

        // ---- 4. cross-warp carries (vector form) ----
        float fc0 = 0.f, fc1 = 0.f;
        if (wp >= 1) { M2 T = ld4(s_wtF[0]); apply0(T, fc0, fc1); }
        if (wp >= 2) { M2 T = ld4(s_wtF[1]); applyv(T, fc0, fc1); }
        if (wp >= 3) { M2 T = ld4(s_wtF[2]); applyv(T, fc0, fc1); }
        float gc0 = 0.f, gc1 = 0.f;
        if (wp <= 2) { M2 T = ld4(s_wtB[3]); apply0(T, gc0, gc1); }
        if (wp <= 1) { M2 T = ld4(s_wtB[2]); applyv(T, gc0, gc1); }
        if (wp == 0) { M2 T = ld4(s_wtB[1]); applyv(T, gc0, gc1); }

        // within-warp boundary messages
        M2 sp = shfl_up_m2(curF, 1);
        float f0 = fc0, f1 = fc1;               // fwd msg at segment start (pos 0)
        if (lane > 0) applyv(sp, f0, f1);
        M2 sn = shfl_dn_m2(curB, 1);
        float g0 = gc0, g1 = gc1;               // bwd msg at segment end (pos 31)
        if (lane < 31) applyv(sn, g0, g1);

        // ---- 5. forward replay: 2 interleaved 16-step chains ----
        u64 mA = pk2(f0, f1);
        float fB0 = f0, fB1 = f1; applyv(P2, fB0, fB1);   // fwd msg at pos 16
        u64 mB = pk2(fB0, fB1);
        #pragma unroll
        for (int k4 = 0; k4 < 4; k4++) {
            float4 vA0, vA1, vB0, vB1;
            #pragma unroll
            for (int c = 0; c < 4; c++) {
                const int kA = k4 * 4 + c;
                const int kB = kA + 16;
                u64 dcA = ((w >> kA) & 1u) ? dc1p : dc0p;
                u64 dcB = ((w >> kB) & 1u) ? dc1p : dc0p;
                u64 xA = fadd2(mA, dcA);
                u64 xB = fadd2(mB, dcB);
                float al, ah, bl, bh; upk2(al, ah, xA); upk2(bl, bh, xB);
                if (c == 0)      { vA0.x = al; vA1.x = ah; vB0.x = bl; vB1.x = bh; }
                else if (c == 1) { vA0.y = al; vA1.y = ah; vB0.y = bl; vB1.y = bh; }
                else if (c == 2) { vA0.z = al; vA1.z = ah; vB0.z = bl; vB1.z = bh; }
                else             { vA0.w = al; vA1.w = ah; vB0.w = bl; vB1.w = bh; }
                if (!(k4 == 3 && c == 3)) {
                    u64 pA = fadd2(xA, aa), qA = fadd2(xA, na);
                    u64 pB = fadd2(xB, aa), qB = fadd2(xB, na);
                    float p0,p1,q0,q1;
                    upk2(p0,p1,pA); upk2(q0,q1,qA); mA = pk2(fmaxf(p0,q1), fmaxf(q0,p1));
                    upk2(p0,p1,pB); upk2(q0,q1,qB); mB = pk2(fmaxf(p0,q1), fmaxf(q0,p1));
                }
            }
            const int sA = (k4 + rot) & 7;
            const int sB = (k4 + 4 + rot) & 7;
            pb0[rowb + sA] = vA0;  pb1[rowb + sA] = vA1;
            pb0[rowb + sB] = vB0;  pb1[rowb + sB] = vB1;
        }

        // ---- 6. backward replay: 2 interleaved chains; combine + exp2 fused ----
        u64 nB = pk2(g0, g1);                               // bwd at pos 31
        float gl0 = g0, gl1 = g1; applyv(U23, gl0, gl1);    // bwd at pos 15
        u64 nA = pk2(gl0, gl1);
        #pragma unroll
        for (int k4 = 3; k4 >= 0; k4--) {
            float4 nA0, nA1, nB0, nB1;
            #pragma unroll
            for (int c = 3; c >= 0; c--) {
                const int pA = k4 * 4 + c;                 // local pos 15..0
                const int pB = pA + 16;
                float al, ah, bl, bh; upk2(al, ah, nA); upk2(bl, bh, nB);
                if (c == 0)      { nA0.x = al; nA1.x = ah; nB0.x = bl; nB1.x = bh; }
                else if (c == 1) { nA0.y = al; nA1.y = ah; nB0.y = bl; nB1.y = bh; }
                else if (c == 2) { nA0.z = al; nA1.z = ah; nB0.z = bl; nB1.z = bh; }
                else             { nA0.w = al; nA1.w = ah; nB0.w = bl; nB1.w = bh; }
                if (pA > 0) {
                    u64 dcA = ((w >> pA) & 1u) ? dc1p : dc0p;
                    u64 dcB = ((w >> pB) & 1u) ? dc1p : dc0p;
                    nA = step2(nA, dcA, aa, na);
                    nB = step2(nB, dcB, aa, na);
                }
            }
            const int sA = (k4 + rot) & 7;
            const int sB = (k4 + 4 + rot) & 7;
            {
                float4 fv0 = pb0[rowb + sA];
                float4 fv1 = pb1[rowb + sA];
                u64 s0a = fadd2(pk2(fv0.x, fv0.y), pk2(nA0.x, nA0.y));
                u64 s0b = fadd2(pk2(fv0.z, fv0.w), pk2(nA0.z, nA0.w));
                u64 s1a = fadd2(pk2(fv1.x, fv1.y), pk2(nA1.x, nA1.y));
                u64 s1b = fadd2(pk2(fv1.z, fv1.w), pk2(nA1.z, nA1.w));
                float4 o0v, o1v; float lo, hi;
                upk2(lo, hi, s0a); o0v.x = ex2(lo); o0v.y = ex2(hi);
                upk2(lo, hi, s0b); o0v.z = ex2(lo); o0v.w = ex2(hi);
                upk2(lo, hi, s1a); o1v.x = ex2(lo); o1v.y = ex2(hi);
                upk2(lo, hi, s1b); o1v.z = ex2(lo); o1v.w = ex2(hi);
                pb0[rowb + sA] = o0v;
                pb1[rowb + sA] = o1v;
            }
            {
                float4 fv0 = pb0[rowb + sB];
                float4 fv1 = pb1[rowb + sB];
                u64 s0a = fadd2(pk2(fv0.x, fv0.y), pk2(nB0.x, nB0.y));
                u64 s0b = fadd2(pk2(fv0.z, fv0.w), pk2(nB0.z, nB0.w));
                u64 s1a = fadd2(pk2(fv1.x, fv1.y), pk2(nB1.x, nB1.y));
                u64 s1b = fadd2(pk2(fv1.z, fv1.w), pk2(nB1.z, nB1.w));
                float4 o0v, o1v; float lo, hi;
                upk2(lo, hi, s0a); o0v.x = ex2(lo); o0v.y = ex2(hi);
                upk2(lo, hi, s0b); o0v.z = ex2(lo); o0v.w = ex2(hi);
                upk2(lo, hi, s1a); o1v.x = ex2(lo); o1v.y = ex2(hi);
                upk2(lo, hi, s1b); o1v.z = ex2(lo); o1v.w = ex2(hi);
                pb0[rowb + sB] = o0v;
                pb1[rowb + sB] = o1v;
            }
        }
        __syncthreads();

        // ---- 7. epilogue: LDS.128 -> STG.128 coalesced ----
        float4* o0 = (float4*)(out + (size_t)row * 2 * CH_L);
        float4* o1 = o0 + (CH_L / 4);
        #pragma unroll
        for (int it = 0; it < 8; it++) {
            const int u    = tid + CH_T * it;
            const int blk  = u >> 3;
            const int k4   = u & 7;
            const int slot = (k4 + (blk & 7)) & 7;
            o0[u] = pb0[blk * 8 + slot];
            o1[u] = pb1[blk * 8 + slot];
        }
        __syncthreads();   // pb + s_wt reuse barrier before next row
    }
}

extern "C" void kernel_launch(void* const* d_in, const int* in_sizes, int n_in,
                              void* d_out, int out_size) {
    const float* jp  = (const float*)d_in[0];
    const float* bp  = (const float*)d_in[1];
    const int*   obs = (const int*)  d_in[2];
    float*       out = (float*)d_out;

    int B = in_sizes[2] / CH_L;
    int grid = 148 * 6;
    if (grid > B) grid = B;
    chain_bp_kernel<<<grid, CH_T>>>(jp, bp, obs, out, B);
}

// round 11
// speedup vs baseline: 1.0819x; 1.0031x over previous
#include <cuda_runtime.h>

#define CH_L   4096
#define CH_T   128
#define NEG_INF (-1e30f)
#define LOG2E  1.4426950408889634f

typedef unsigned long long u64;

struct M2 { float a00, a01, a10, a11; };  // max-plus 2x2 operator (log2 domain)

__device__ __forceinline__ void step_vec(float& m0, float& m1, float c, float a) {
    float x0 = m0 - c;
    float x1 = m1 + c;
    m0 = fmaxf(x0 + a, x1 - a);
    m1 = fmaxf(x0 - a, x1 + a);
}
__device__ __forceinline__ void step_mat(M2& M, float c, float a) {
    step_vec(M.a00, M.a10, c, a);
    step_vec(M.a01, M.a11, c, a);
}
// C = A ∘ B (B applied first)
__device__ __forceinline__ M2 compose(const M2& A, const M2& B) {
    M2 C;
    C.a00 = fmaxf(A.a00 + B.a00, A.a01 + B.a10);
    C.a01 = fmaxf(A.a00 + B.a01, A.a01 + B.a11);
    C.a10 = fmaxf(A.a10 + B.a00, A.a11 + B.a10);
    C.a11 = fmaxf(A.a10 + B.a01, A.a11 + B.a11);
    return C;
}
__device__ __forceinline__ M2 m2_identity() { return M2{0.f, NEG_INF, NEG_INF, 0.f}; }

// v = M · (0,0)
__device__ __forceinline__ void apply0(const M2& M, float& v0, float& v1) {
    v0 = fmaxf(M.a00, M.a01);
    v1 = fmaxf(M.a10, M.a11);
}
// v = M · v
__device__ __forceinline__ void applyv(const M2& M, float& v0, float& v1) {
    float r0 = fmaxf(M.a00 + v0, M.a01 + v1);
    float r1 = fmaxf(M.a10 + v0, M.a11 + v1);
    v0 = r0; v1 = r1;
}

// ---- packed f32x2 helpers ----
__device__ __forceinline__ u64 pk2(float lo, float hi) {
    u64 r; asm("mov.b64 %0, {%1,%2};" : "=l"(r) : "f"(lo), "f"(hi)); return r;
}
__device__ __forceinline__ void upk2(float& lo, float& hi, u64 v) {
    asm("mov.b64 {%0,%1}, %2;" : "=f"(lo), "=f"(hi) : "l"(v));
}
__device__ __forceinline__ u64 fadd2(u64 a, u64 b) {
    u64 r; asm("add.rn.f32x2 %0, %1, %2;" : "=l"(r) : "l"(a), "l"(b)); return r;
}
__device__ __forceinline__ float ex2(float x) {
    float r; asm("ex2.approx.f32 %0, %1;" : "=f"(r) : "f"(x)); return r;
}
__device__ __forceinline__ u64 step2(u64 m, u64 dc, u64 aa, u64 na) {
    u64 x = fadd2(m, dc);
    u64 p = fadd2(x, aa), q = fadd2(x, na);
    float pl, ph, ql, qh; upk2(pl, ph, p); upk2(ql, qh, q);
    return pk2(fmaxf(pl, qh), fmaxf(ql, ph));
}

__device__ __forceinline__ M2 ld4(float4 v) { return M2{v.x, v.y, v.z, v.w}; }

__device__ __forceinline__ M2 shfl_up_m2(M2 m, int d) {
    M2 r;
    r.a00 = __shfl_up_sync(0xffffffffu, m.a00, d);
    r.a01 = __shfl_up_sync(0xffffffffu, m.a01, d);
    r.a10 = __shfl_up_sync(0xffffffffu, m.a10, d);
    r.a11 = __shfl_up_sync(0xffffffffu, m.a11, d);
    return r;
}
__device__ __forceinline__ M2 shfl_dn_m2(M2 m, int d) {
    M2 r;
    r.a00 = __shfl_down_sync(0xffffffffu, m.a00, d);
    r.a01 = __shfl_down_sync(0xffffffffu, m.a01, d);
    r.a10 = __shfl_down_sync(0xffffffffu, m.a10, d);
    r.a11 = __shfl_down_sync(0xffffffffu, m.a11, d);
    return r;
}

__global__ __launch_bounds__(CH_T, 8)
void chain_bp_kernel(const float* __restrict__ jp,
                     const float* __restrict__ bp,
                     const int*   __restrict__ obs,
                     float*       __restrict__ out,
                     int nrows) {
    __shared__ float4 s_tab[256];        // 8-step operator table (4 KB)
    __shared__ float  sb0[CH_L / 2];     // half-row belief scratch, state 0 (8 KB)
    __shared__ float  sb1[CH_L / 2];     // state 1 (8 KB)
    __shared__ float4 s_wtF[4];
    __shared__ float4 s_wtB[4];

    const int tid  = threadIdx.x;
    const int lane = tid & 31;
    const int wp   = tid >> 5;

    const float a  = 0.25f * jp[0] * LOG2E;
    const float c0 = 0.5f  * bp[0] * LOG2E;
    const float c1 = 0.5f  * bp[1] * LOG2E;

    // ---- 0. per-block table build (amortized over ~3.5 rows) ----
    #pragma unroll
    for (int e = 0; e < 2; e++) {
        int x = tid + e * CH_T;
        M2 M = m2_identity();
        #pragma unroll
        for (int k = 0; k < 8; k++) {
            float c = ((x >> k) & 1) ? c1 : c0;
            step_mat(M, c, a);
        }
        s_tab[x] = make_float4(M.a00, M.a01, M.a10, M.a11);
    }
    __syncthreads();

    // ---- packed constants ----
    const u64 dc0p = pk2(-c0,  c0);
    const u64 dc1p = pk2(-c1,  c1);
    const u64 aa   = pk2( a,   a);
    const u64 na   = pk2(-a,  -a);

    float4* pb0 = (float4*)sb0;
    float4* pb1 = (float4*)sb1;
    const int rowb = tid * 4;            // my 4 float4 slots per state per chunk
    const int rot  = (tid >> 1) & 3;     // slot rotation (conflict-free phases)
    const int wbase = wp << 10;

    for (int row = blockIdx.x; row < nrows; row += gridDim.x) {

        // ---- 1. obs ingest, warp-local: lane k keeps ballot word k ----
        unsigned int w = 0;
        const int* orow = obs + (size_t)row * CH_L;
        #pragma unroll
        for (int i = 0; i < 32; i++) {
            int o = orow[wbase + (i << 5) + lane];
            unsigned int bal = __ballot_sync(0xffffffffu, o != 0);
            if (i == lane) w = bal;
        }

        // ---- 2. segment operators + partials (seeds derived below) ----
        M2 tb0 = ld4(s_tab[ w        & 255u]);
        M2 tb1 = ld4(s_tab[(w >>  8) & 255u]);
        M2 tb2 = ld4(s_tab[(w >> 16) & 255u]);
        M2 tb3 = ld4(s_tab[(w >> 24) & 255u]);
        M2 P2 = compose(tb1, tb0);                 // fwd op for bits 0..15
        M2 F  = compose(tb3, compose(tb2, P2));

        M2 uB0 = ld4(s_tab[__brev( w        & 255u) >> 24]);
        M2 uB1 = ld4(s_tab[__brev((w >>  8) & 255u) >> 24]);
        M2 uB2 = ld4(s_tab[__brev((w >> 16) & 255u) >> 24]);
        M2 uB3 = ld4(s_tab[__brev((w >> 24) & 255u) >> 24]);
        M2 U23 = compose(uB2, uB3);                // bwd op for pos 16..31
        M2 Bm  = compose(uB0, compose(uB1, U23));

        // ---- 3. merged warp scans: fwd prefix + bwd suffix ----
        M2 curF = F, curB = Bm;
        #pragma unroll
        for (int off = 1; off < 32; off <<= 1) {
            M2 lF = shfl_up_m2(curF, off);
            M2 rB = shfl_dn_m2(curB, off);
            if (lane >= off)      curF = compose(curF, lF);
            if (lane + off < 32)  curB = compose(curB, rB);
        }
        if (lane == 31) s_wtF[wp] = make_float4(curF.a00, curF.a01, curF.a10, curF.a11);
        if (lane == 0)  s_wtB[wp] = make_float4(curB.a00, curB.a01, curB.a10, curB.a11);
        __syncthreads();

        // ---- 4. cross-warp carries (vector form) ----
        float fc0 = 0.f, fc1 = 0.f;
        if (wp >= 1) { M2 T = ld4(s_wtF[0]); apply0(T, fc0, fc1); }
        if (wp >= 2) { M2 T = ld4(s_wtF[1]); applyv(T, fc0, fc1); }
        if (wp >= 3) { M2 T = ld4(s_wtF[2]); applyv(T, fc0, fc1); }
        float gc0 = 0.f, gc1 = 0.f;
        if (wp <= 2) { M2 T = ld4(s_wtB[3]); apply0(T, gc0, gc1); }
        if (wp <= 1) { M2 T = ld4(s_wtB[2]); applyv(T, gc0, gc1); }
        if (wp == 0) { M2 T = ld4(s_wtB[1]); applyv(T, gc0, gc1); }

        // within-warp boundary messages
        M2 sp = shfl_up_m2(curF, 1);
        float f0 = fc0, f1 = fc1;               // fwd msg at segment pos 0
        if (lane > 0) applyv(sp, f0, f1);
        M2 sn = shfl_dn_m2(curB, 1);
        float g0 = gc0, g1 = gc1;               // bwd msg at segment pos 31
        if (lane < 31) applyv(sn, g0, g1);

        // ---- 5. all chain seeds upfront (tables die here) ----
        // fwd seeds: pos 0 / 8 / 16 / 24
        float sA0l = f0, sA0h = f1;
        float sB0l = f0, sB0h = f1; applyv(tb0, sB0l, sB0h);
        float sA1l = f0, sA1h = f1; applyv(P2,  sA1l, sA1h);
        float sB1l = sA1l, sB1h = sA1h; applyv(tb2, sB1l, sB1h);
        // bwd seeds: pos 31 / 23 / 15 / 7
        float bB1l = g0, bB1h = g1;
        float bA1l = g0, bA1h = g1; applyv(uB3, bA1l, bA1h);
        float bB0l = g0, bB0h = g1; applyv(U23, bB0l, bB0h);
        float bA0l = bB0l, bA0h = bB0h; applyv(uB1, bA0l, bA0h);

        // ---- 6. two half-segment chunks: replay + output ----
        #pragma unroll
        for (int h = 0; h < 2; h++) {
            const int kb = h << 4;               // chunk bit base

            // -- fwd replay: 2 interleaved 8-step chains --
            u64 mA = h ? pk2(sA1l, sA1h) : pk2(sA0l, sA0h);
            u64 mB = h ? pk2(sB1l, sB1h) : pk2(sB0l, sB0h);
            #pragma unroll
            for (int k4 = 0; k4 < 2; k4++) {
                float4 vA0, vA1, vB0, vB1;
                #pragma unroll
                for (int c = 0; c < 4; c++) {
                    const int kA = kb + k4 * 4 + c;
                    const int kB = kA + 8;
                    u64 dcA = ((w >> kA) & 1u) ? dc1p : dc0p;
                    u64 dcB = ((w >> kB) & 1u) ? dc1p : dc0p;
                    u64 xA = fadd2(mA, dcA);
                    u64 xB = fadd2(mB, dcB);
                    float al, ah, bl, bh; upk2(al, ah, xA); upk2(bl, bh, xB);
                    if (c == 0)      { vA0.x = al; vA1.x = ah; vB0.x = bl; vB1.x = bh; }
                    else if (c == 1) { vA0.y = al; vA1.y = ah; vB0.y = bl; vB1.y = bh; }
                    else if (c == 2) { vA0.z = al; vA1.z = ah; vB0.z = bl; vB1.z = bh; }
                    else             { vA0.w = al; vA1.w = ah; vB0.w = bl; vB1.w = bh; }
                    if (!(k4 == 1 && c == 3)) {
                        u64 pA = fadd2(xA, aa), qA = fadd2(xA, na);
                        u64 pB = fadd2(xB, aa), qB = fadd2(xB, na);
                        float p0,p1,q0,q1;
                        upk2(p0,p1,pA); upk2(q0,q1,qA); mA = pk2(fmaxf(p0,q1), fmaxf(q0,p1));
                        upk2(p0,p1,pB); upk2(q0,q1,qB); mB = pk2(fmaxf(p0,q1), fmaxf(q0,p1));
                    }
                }
                const int sA = (k4 + rot) & 3;       // chain A -> local j = k4
                const int sB = (k4 + 2 + rot) & 3;   // chain B -> local j = 2+k4
                pb0[rowb + sA] = vA0;  pb1[rowb + sA] = vA1;
                pb0[rowb + sB] = vB0;  pb1[rowb + sB] = vB1;
            }

            // -- bwd replay (self-slots, no sync): combine + exp2 --
            u64 nA = h ? pk2(bA1l, bA1h) : pk2(bA0l, bA0h);  // local pos 7
            u64 nB = h ? pk2(bB1l, bB1h) : pk2(bB0l, bB0h);  // local pos 15
            #pragma unroll
            for (int k4 = 1; k4 >= 0; k4--) {
                float4 nA0, nA1, nB0, nB1;
                #pragma unroll
                for (int c = 3; c >= 0; c--) {
                    const int p = k4 * 4 + c;             // chain-local pos 7..0
                    float al, ah, bl, bh; upk2(al, ah, nA); upk2(bl, bh, nB);
                    if (c == 0)      { nA0.x = al; nA1.x = ah; nB0.x = bl; nB1.x = bh; }
                    else if (c == 1) { nA0.y = al; nA1.y = ah; nB0.y = bl; nB1.y = bh; }
                    else if (c == 2) { nA0.z = al; nA1.z = ah; nB0.z = bl; nB1.z = bh; }
                    else             { nA0.w = al; nA1.w = ah; nB0.w = bl; nB1.w = bh; }
                    if (p > 0) {
                        u64 dcA = ((w >> (kb + p))     & 1u) ? dc1p : dc0p;
                        u64 dcB = ((w >> (kb + 8 + p)) & 1u) ? dc1p : dc0p;
                        nA = step2(nA, dcA, aa, na);
                        nB = step2(nB, dcB, aa, na);
                    }
                }
                const int sA = (k4 + rot) & 3;
                const int sB = (k4 + 2 + rot) & 3;
                {
                    float4 fv0 = pb0[rowb + sA];
                    float4 fv1 = pb1[rowb + sA];
                    u64 s0a = fadd2(pk2(fv0.x, fv0.y), pk2(nA0.x, nA0.y));
                    u64 s0b = fadd2(pk2(fv0.z, fv0.w), pk2(nA0.z, nA0.w));
                    u64 s1a = fadd2(pk2(fv1.x, fv1.y), pk2(nA1.x, nA1.y));
                    u64 s1b = fadd2(pk2(fv1.z, fv1.w), pk2(nA1.z, nA1.w));
                    float4 o0v, o1v; float lo, hi;
                    upk2(lo, hi, s0a); o0v.x = ex2(lo); o0v.y = ex2(hi);
                    upk2(lo, hi, s0b); o0v.z = ex2(lo); o0v.w = ex2(hi);
                    upk2(lo, hi, s1a); o1v.x = ex2(lo); o1v.y = ex2(hi);
                    upk2(lo, hi, s1b); o1v.z = ex2(lo); o1v.w = ex2(hi);
                    pb0[rowb + sA] = o0v;
                    pb1[rowb + sA] = o1v;
                }
                {
                    float4 fv0 = pb0[rowb + sB];
                    float4 fv1 = pb1[rowb + sB];
                    u64 s0a = fadd2(pk2(fv0.x, fv0.y), pk2(nB0.x, nB0.y));
                    u64 s0b = fadd2(pk2(fv0.z, fv0.w), pk2(nB0.z, nB0.w));
                    u64 s1a = fadd2(pk2(fv1.x, fv1.y), pk2(nB1.x, nB1.y));
                    u64 s1b = fadd2(pk2(fv1.z, fv1.w), pk2(nB1.z, nB1.w));
                    float4 o0v, o1v; float lo, hi;
                    upk2(lo, hi, s0a); o0v.x = ex2(lo); o0v.y = ex2(hi);
                    upk2(lo, hi, s0b); o0v.z = ex2(lo); o0v.w = ex2(hi);
                    upk2(lo, hi, s1a); o1v.x = ex2(lo); o1v.y = ex2(hi);
                    upk2(lo, hi, s1b); o1v.z = ex2(lo); o1v.w = ex2(hi);
                    pb0[rowb + sB] = o0v;
                    pb1[rowb + sB] = o1v;
                }
            }
            __syncthreads();

            // -- chunk epilogue: LDS.128 -> STG.128 (64B-contiguous runs) --
            float4* o0 = (float4*)(out + (size_t)row * 2 * CH_L);
            float4* o1 = o0 + (CH_L / 4);
            #pragma unroll
            for (int it = 0; it < 4; it++) {
                const int u    = tid + CH_T * it;   // chunk float4 index 0..511
                const int b    = u >> 2;            // producing thread
                const int j    = u & 3;             // logical slot
                const int slot = (j + ((b >> 1) & 3)) & 3;
                const int g    = b * 8 + (h << 2) + j;  // global float4 index
                o0[g] = pb0[b * 4 + slot];
                o1[g] = pb1[b * 4 + slot];
            }
            __syncthreads();   // buffer reuse barrier (next chunk / next row)
        }
    }
}

extern "C" void kernel_launch(void* const* d_in, const int* in_sizes, int n_in,
                              void* d_out, int out_size) {
    const float* jp  = (const float*)d_in[0];
    const float* bp  = (const float*)d_in[1];
    const int*   obs = (const int*)  d_in[2];
    float*       out = (float*)d_out;

    int B = in_sizes[2] / CH_L;
    int grid = 148 * 8;
    if (grid > B) grid = B;
    chain_bp_kernel<<<grid, CH_T>>>(jp, bp, obs, out, B);
}